// round 10
// baseline (speedup 1.0000x reference)
#include <cuda_runtime.h>

#define NQ  512
#define NKV 512
#define DD  64
#define QT  4

typedef unsigned long long ull;

// proj scratch [b][k][c][e]; pad covers unconditional proj prefetch overrun
// (up to 2 stages = 16 rows * 192 floats past the end for b=3)
__device__ float g_proj[4 * NKV * 3 * DD + 4096];

// ---- packed fp32x2 math (per-lane IEEE fp32, identical rounding to scalar) ----
#define PACK2(d, lo, hi)   asm("mov.b64 %0, {%1, %2};" : "=l"(d) : "f"(lo), "f"(hi))
#define UNPACK2(lo, hi, s) asm("mov.b64 {%0, %1}, %2;" : "=f"(lo), "=f"(hi) : "l"(s))
#define FMA2(d, a, b, c)   asm("fma.rn.f32x2 %0, %1, %2, %3;" : "=l"(d) : "l"(a), "l"(b), "l"(c))
#define ADD2(d, a, b)      asm("add.rn.f32x2 %0, %1, %2;" : "=l"(d) : "l"(a), "l"(b))

// Predicated 8-byte load. flag==0: NO memory access, dst = {-inf,-inf}.
// exp(-inf) = +0 exactly, so masked k contribute exactly 0 to every
// accumulator — matching the reference's exp(-1e10-max) fp32 underflow —
// with zero consume-side select/flag instructions.
#define PLDU(dst, flag, ptr)                                            \
    asm("{\n\t.reg .pred p;\n\t"                                        \
        "setp.ne.u32 p, %1, 0;\n\t"                                     \
        "mov.b64 %0, 0xFF800000FF800000;\n\t"                           \
        "@p ld.global.nc.b64 %0, [%2];\n\t}"                            \
        : "=l"(dst) : "r"(flag), "l"(ptr))

// ---------------------------------------------------------------------------
// Kernel A: proj[b,k,c,e] = sum_d v_equi[b,k,c,d] * w_coord[e,d]
// ---------------------------------------------------------------------------
__global__ __launch_bounds__(192) void proj_kernel(const float* __restrict__ v,
                                                   const float* __restrict__ w)
{
    __shared__ float ws[DD][68];
    __shared__ float vs[8 * 3 * DD];

    const int tid = threadIdx.x;
    const float4* w4 = (const float4*)w;
    for (int i = tid; i < DD * DD / 4; i += 192) {
        float4 t = w4[i];
        int e = i >> 4, d = (i & 15) * 4;
        *(float4*)&ws[e][d] = t;
    }
    const int bk0 = blockIdx.x * 8;
    const float4* v4 = (const float4*)(v + (size_t)bk0 * 3 * DD);
    for (int i = tid; i < 8 * 3 * DD / 4; i += 192)
        ((float4*)vs)[i] = v4[i];
    __syncthreads();

    const int c = tid / DD, e = tid % DD;
    float acc[8];
    #pragma unroll
    for (int kk = 0; kk < 8; ++kk) acc[kk] = 0.f;

    #pragma unroll 4
    for (int d4 = 0; d4 < 16; ++d4) {
        const float4 wv = *(const float4*)&ws[e][d4 * 4];
        #pragma unroll
        for (int kk = 0; kk < 8; ++kk) {
            const float4 vv = *(const float4*)&vs[(kk * 3 + c) * DD + d4 * 4];
            acc[kk] += vv.x * wv.x + vv.y * wv.y + vv.z * wv.z + vv.w * wv.w;
        }
    }
    #pragma unroll
    for (int kk = 0; kk < 8; ++kk)
        g_proj[(size_t)(bk0 + kk) * (3 * DD) + c * DD + e] = acc[kk];
}

// ---------------------------------------------------------------------------
// Kernel B: fused masked-softmax attention + L2-norm weighting + w_attn proj.
// Block = (b, 4 q's); grid = 512; 3 CTAs/SM (launch_bounds cap 85 regs).
// x = 32 lanes (2 channels each, f32x2), y = 8 k-slices (k = y + 8*stage).
// Depth-2 register pipeline on messages (bufA/bufB, unroll-2 body) and
// double-buffered proj rows. Masks live in per-q 64-bit shift registers.
// ---------------------------------------------------------------------------
__global__ __launch_bounds__(256, 3) void attn_kernel(
    const float* __restrict__ messages,
    const int*   __restrict__ adj,
    const float* __restrict__ w_attn,
    float*       __restrict__ out)
{
    __shared__ float wat[DD * 65];             // w_attn^T, pad 65
    __shared__ ull   redu[8][32][5];
    __shared__ float pre[QT][3][DD];

    const int x   = threadIdx.x;
    const int y   = threadIdx.y;
    const int tid = y * 32 + x;
    const int b   = blockIdx.x >> 7;           // NQ/QT = 128 q-tiles per batch
    const int q0  = (blockIdx.x & 127) * QT;

    // w_attn -> smem transposed now; consumed only after the mainloop
    for (int i = tid; i < DD * DD; i += 256) {
        int e = i >> 6, d = i & 63;
        wat[d * 65 + e] = w_attn[i];
    }

    // Masks as 64-bit shift registers: bit j (of hi:lo) = adj(q, k = y+8j).
    unsigned mlo[QT], mhi[QT];
    {
        const int* adjb = adj + ((size_t)b * NQ + q0) * NKV;
        #pragma unroll
        for (int q = 0; q < QT; ++q) {
            mlo[q] = __ballot_sync(0xffffffffu, adjb[q * NKV + y + 8 * x] > 0);
            mhi[q] = __ballot_sync(0xffffffffu, adjb[q * NKV + y + 256 + 8 * x] > 0);
        }
    }

    // Accumulators (packed f32x2): 5 per q
    ull sv[QT], s2v[QT], a0v[QT], a1v[QT], a2v[QT];
    #pragma unroll
    for (int q = 0; q < QT; ++q) { sv[q]=0; s2v[q]=0; a0v[q]=0; a1v[q]=0; a2v[q]=0; }

    // msg: stage s at mp + s*256 (float2), q at compile-time offset q*16384
    const float2* mp = (const float2*)messages
                     + (size_t)(b * NQ + q0) * (NKV * 32) + y * 32 + x;
    // proj: stage s at pp + s*768 (ull), components at +0/+32/+64
    const ull* pp = (const ull*)g_proj + (size_t)b * NKV * 96 + y * 96 + x;

    // ---- prime: messages stages 0,1; proj stages 0,1 ----
    ull bufA[QT], bufB[QT];
    #pragma unroll
    for (int q = 0; q < QT; ++q) {
        PLDU(bufA[q], mlo[q] & 1u, mp + 0 * 256 + q * 16384);
        PLDU(bufB[q], mlo[q] & 2u, mp + 1 * 256 + q * 16384);
    }
    ull pjA0 = pp[0],       pjA1 = pp[32],       pjA2 = pp[64];
    ull pjB0 = pp[768],     pjB1 = pp[768 + 32], pjB2 = pp[768 + 64];

    const float2* mp2 = mp + 2 * 256;          // prefetch cursor: stage i+2
    const ull*    pp2 = pp + 2 * 768;

    #pragma unroll 1
    for (int it = 0; it < 32; ++it) {
        // flags for prefetch stages i+2 (bit 2) and i+3 (bit 3)
        unsigned fA0 = mlo[0] & 4u, fB0 = mlo[0] & 8u;
        unsigned fA1 = mlo[1] & 4u, fB1 = mlo[1] & 8u;
        unsigned fA2 = mlo[2] & 4u, fB2 = mlo[2] & 8u;
        unsigned fA3 = mlo[3] & 4u, fB3 = mlo[3] & 8u;
        #pragma unroll
        for (int q = 0; q < QT; ++q) {
            mlo[q] = __funnelshift_r(mlo[q], mhi[q], 2);
            mhi[q] >>= 2;
        }

        // ======== half A: stage 2*it ========
        ull ev0, ev1, ev2, ev3;
        {
            float mx, my, e0, e1;
            UNPACK2(mx, my, bufA[0]); e0=__expf(mx); e1=__expf(my); PACK2(ev0, e0, e1);
            UNPACK2(mx, my, bufA[1]); e0=__expf(mx); e1=__expf(my); PACK2(ev1, e0, e1);
            UNPACK2(mx, my, bufA[2]); e0=__expf(mx); e1=__expf(my); PACK2(ev2, e0, e1);
            UNPACK2(mx, my, bufA[3]); e0=__expf(mx); e1=__expf(my); PACK2(ev3, e0, e1);
        }
        PLDU(bufA[0], fA0, mp2 + 0 * 16384);
        PLDU(bufA[1], fA1, mp2 + 1 * 16384);
        PLDU(bufA[2], fA2, mp2 + 2 * 16384);
        PLDU(bufA[3], fA3, mp2 + 3 * 16384);
        ADD2(sv[0], sv[0], ev0); FMA2(s2v[0], ev0, ev0, s2v[0]);
        FMA2(a0v[0], ev0, pjA0, a0v[0]); FMA2(a1v[0], ev0, pjA1, a1v[0]); FMA2(a2v[0], ev0, pjA2, a2v[0]);
        ADD2(sv[1], sv[1], ev1); FMA2(s2v[1], ev1, ev1, s2v[1]);
        FMA2(a0v[1], ev1, pjA0, a0v[1]); FMA2(a1v[1], ev1, pjA1, a1v[1]); FMA2(a2v[1], ev1, pjA2, a2v[1]);
        ADD2(sv[2], sv[2], ev2); FMA2(s2v[2], ev2, ev2, s2v[2]);
        FMA2(a0v[2], ev2, pjA0, a0v[2]); FMA2(a1v[2], ev2, pjA1, a1v[2]); FMA2(a2v[2], ev2, pjA2, a2v[2]);
        ADD2(sv[3], sv[3], ev3); FMA2(s2v[3], ev3, ev3, s2v[3]);
        FMA2(a0v[3], ev3, pjA0, a0v[3]); FMA2(a1v[3], ev3, pjA1, a1v[3]); FMA2(a2v[3], ev3, pjA2, a2v[3]);
        // refill pjA with stage 2*it+2 (unconditional; pad absorbs overrun)
        pjA0 = pp2[0]; pjA1 = pp2[32]; pjA2 = pp2[64];

        // ======== half B: stage 2*it+1 ========
        {
            float mx, my, e0, e1;
            UNPACK2(mx, my, bufB[0]); e0=__expf(mx); e1=__expf(my); PACK2(ev0, e0, e1);
            UNPACK2(mx, my, bufB[1]); e0=__expf(mx); e1=__expf(my); PACK2(ev1, e0, e1);
            UNPACK2(mx, my, bufB[2]); e0=__expf(mx); e1=__expf(my); PACK2(ev2, e0, e1);
            UNPACK2(mx, my, bufB[3]); e0=__expf(mx); e1=__expf(my); PACK2(ev3, e0, e1);
        }
        PLDU(bufB[0], fB0, mp2 + 256 + 0 * 16384);
        PLDU(bufB[1], fB1, mp2 + 256 + 1 * 16384);
        PLDU(bufB[2], fB2, mp2 + 256 + 2 * 16384);
        PLDU(bufB[3], fB3, mp2 + 256 + 3 * 16384);
        ADD2(sv[0], sv[0], ev0); FMA2(s2v[0], ev0, ev0, s2v[0]);
        FMA2(a0v[0], ev0, pjB0, a0v[0]); FMA2(a1v[0], ev0, pjB1, a1v[0]); FMA2(a2v[0], ev0, pjB2, a2v[0]);
        ADD2(sv[1], sv[1], ev1); FMA2(s2v[1], ev1, ev1, s2v[1]);
        FMA2(a0v[1], ev1, pjB0, a0v[1]); FMA2(a1v[1], ev1, pjB1, a1v[1]); FMA2(a2v[1], ev1, pjB2, a2v[1]);
        ADD2(sv[2], sv[2], ev2); FMA2(s2v[2], ev2, ev2, s2v[2]);
        FMA2(a0v[2], ev2, pjB0, a0v[2]); FMA2(a1v[2], ev2, pjB1, a1v[2]); FMA2(a2v[2], ev2, pjB2, a2v[2]);
        ADD2(sv[3], sv[3], ev3); FMA2(s2v[3], ev3, ev3, s2v[3]);
        FMA2(a0v[3], ev3, pjB0, a0v[3]); FMA2(a1v[3], ev3, pjB1, a1v[3]); FMA2(a2v[3], ev3, pjB2, a2v[3]);
        // refill pjB with stage 2*it+3
        pjB0 = pp2[768]; pjB1 = pp2[768 + 32]; pjB2 = pp2[768 + 64];

        mp2 += 512;
        pp2 += 1536;
    }

    // Stage 3: reduce 8 k-slices per q; fold weights pre = acc*sqrt(s2)/s^2
    #pragma unroll 1
    for (int q = 0; q < QT; ++q) {
        __syncthreads();
        redu[y][x][0] = sv[q];
        redu[y][x][1] = s2v[q];
        redu[y][x][2] = a0v[q];
        redu[y][x][3] = a1v[q];
        redu[y][x][4] = a2v[q];
        __syncthreads();
        if (tid < 32) {
            ull S  = redu[0][x][0];
            ull S2 = redu[0][x][1];
            ull A0 = redu[0][x][2];
            ull A1 = redu[0][x][3];
            ull A2 = redu[0][x][4];
            #pragma unroll
            for (int yy = 1; yy < 8; ++yy) {
                ADD2(S,  S,  redu[yy][x][0]);
                ADD2(S2, S2, redu[yy][x][1]);
                ADD2(A0, A0, redu[yy][x][2]);
                ADD2(A1, A1, redu[yy][x][3]);
                ADD2(A2, A2, redu[yy][x][4]);
            }
            float Sx, Sy, S2x, S2y, ax, ay;
            UNPACK2(Sx, Sy, S);
            UNPACK2(S2x, S2y, S2);
            const float scx = sqrtf(S2x) / (Sx * Sx);
            const float scy = sqrtf(S2y) / (Sy * Sy);
            float2* pre2 = (float2*)pre;
            UNPACK2(ax, ay, A0); pre2[(q * 3 + 0) * 32 + x] = make_float2(ax * scx, ay * scy);
            UNPACK2(ax, ay, A1); pre2[(q * 3 + 1) * 32 + x] = make_float2(ax * scx, ay * scy);
            UNPACK2(ax, ay, A2); pre2[(q * 3 + 2) * 32 + x] = make_float2(ax * scx, ay * scy);
        }
    }
    __syncthreads();

    // Stage 4: out[q,c,e] = sum_d pre[q,c,d] * w_attn[e,d]   (QT*3*64 = 768)
    float* outb = out + (size_t)(b * NQ + q0) * (3 * DD);
    #pragma unroll
    for (int j = 0; j < 3; ++j) {
        const int oid = tid + j * 256;          // (q*3+c)*64 + e
        const int e  = oid & 63;
        const int cq = oid >> 6;
        const int c  = cq % 3, q = cq / 3;
        float acc = 0.f;
        #pragma unroll
        for (int d = 0; d < DD; ++d)
            acc += pre[q][c][d] * wat[d * 65 + e];
        outb[oid] = acc;
    }
}

// ---------------------------------------------------------------------------
extern "C" void kernel_launch(void* const* d_in, const int* in_sizes, int n_in,
                              void* d_out, int out_size)
{
    const float* v_equi   = (const float*)d_in[0];
    const float* messages = (const float*)d_in[1];
    const int*   adj      = (const int*)d_in[2];
    const float* w_coord  = (const float*)d_in[3];
    const float* w_attn   = (const float*)d_in[4];
    float* out = (float*)d_out;

    const int B = in_sizes[2] / (NQ * NKV);     // adj element count -> batch

    proj_kernel<<<B * NKV / 8, 192>>>(v_equi, w_coord);

    dim3 blk(32, 8);
    attn_kernel<<<B * (NQ / QT), blk>>>(messages, adj, w_attn, out);
}

// round 11
// speedup vs baseline: 1.0422x; 1.0422x over previous
#include <cuda_runtime.h>

#define NQ  512
#define NKV 512
#define DD  64
#define QT  8

typedef unsigned long long ull;

// proj scratch [b][k][c][e]; pad covers depth-1 prefetch overrun past k=511
__device__ __align__(256) float g_proj[4 * NKV * 3 * DD + 8192];

// ---- packed fp32x2 math (per-lane IEEE fp32, identical rounding to scalar) ----
#define PACK2(d, lo, hi)   asm("mov.b64 %0, {%1, %2};" : "=l"(d) : "f"(lo), "f"(hi))
#define UNPACK2(lo, hi, s) asm("mov.b64 {%0, %1}, %2;" : "=f"(lo), "=f"(hi) : "l"(s))
#define FMA2(d, a, b, c)   asm("fma.rn.f32x2 %0, %1, %2, %3;" : "=l"(d) : "l"(a), "l"(b), "l"(c))
#define ADD2(d, a, b)      asm("add.rn.f32x2 %0, %1, %2;" : "=l"(d) : "l"(a), "l"(b))
// raw ex2; e = ex2(m * log2e) with the exact same log2e float __expf uses
#define EX2(d, a)          asm("ex2.approx.f32 %0, %1;" : "=f"(d) : "f"(a))

// Predicated 16-byte load (one LDG.E.128 under @p). flag==0: NO memory
// access, dst = {-inf,-inf,-inf,-inf}; ex2(-inf)=+0 exactly, so masked k
// contribute exactly 0 — matching the reference's exp(-1e10-max) underflow.
#define PLDU128(lo, hi, flag, ptr)                                      \
    asm("{\n\t.reg .pred p;\n\t"                                        \
        "setp.ne.u32 p, %2, 0;\n\t"                                     \
        "mov.b64 %0, 0xFF800000FF800000;\n\t"                           \
        "mov.b64 %1, 0xFF800000FF800000;\n\t"                           \
        "@p ld.global.nc.v2.u64 {%0,%1}, [%3];\n\t}"                    \
        : "=l"(lo), "=l"(hi) : "r"(flag), "l"(ptr))

#define LDG2U64(lo, hi, ptr)                                            \
    asm("ld.global.nc.v2.u64 {%0,%1}, [%2];" : "=l"(lo), "=l"(hi) : "l"(ptr))

// ---------------------------------------------------------------------------
// Kernel A: proj[b,k,c,e] = sum_d v_equi[b,k,c,d] * w_coord[e,d]
// ---------------------------------------------------------------------------
__global__ __launch_bounds__(192) void proj_kernel(const float* __restrict__ v,
                                                   const float* __restrict__ w)
{
    __shared__ float ws[DD][68];
    __shared__ float vs[8 * 3 * DD];

    const int tid = threadIdx.x;
    const float4* w4 = (const float4*)w;
    for (int i = tid; i < DD * DD / 4; i += 192) {
        float4 t = w4[i];
        int e = i >> 4, d = (i & 15) * 4;
        *(float4*)&ws[e][d] = t;
    }
    const int bk0 = blockIdx.x * 8;
    const float4* v4 = (const float4*)(v + (size_t)bk0 * 3 * DD);
    for (int i = tid; i < 8 * 3 * DD / 4; i += 192)
        ((float4*)vs)[i] = v4[i];
    __syncthreads();

    const int c = tid / DD, e = tid % DD;
    float acc[8];
    #pragma unroll
    for (int kk = 0; kk < 8; ++kk) acc[kk] = 0.f;

    #pragma unroll 4
    for (int d4 = 0; d4 < 16; ++d4) {
        const float4 wv = *(const float4*)&ws[e][d4 * 4];
        #pragma unroll
        for (int kk = 0; kk < 8; ++kk) {
            const float4 vv = *(const float4*)&vs[(kk * 3 + c) * DD + d4 * 4];
            acc[kk] += vv.x * wv.x + vv.y * wv.y + vv.z * wv.z + vv.w * wv.w;
        }
    }
    #pragma unroll
    for (int kk = 0; kk < 8; ++kk)
        g_proj[(size_t)(bk0 + kk) * (3 * DD) + c * DD + e] = acc[kk];
}

// ---------------------------------------------------------------------------
// Kernel B: fused masked-softmax attention + L2-norm weighting + w_attn proj.
// Block = (b, 8 q's); grid = 256 -> single wave at 2 CTAs/SM.
// Warp: y = k-slice (k = y + 8*stage). q's processed in PAIRS: lanes 0-15
// handle q=2j (channels 4m..4m+3), lanes 16-31 handle q=2j+1. One predicated
// LDG.128 per pair per stage (halves load-issue and L1 wavefronts vs LDG.64).
// Accumulation order identical to round-9 kernel -> same numerics.
// ---------------------------------------------------------------------------
__global__ __launch_bounds__(256, 2) void attn_kernel(
    const float* __restrict__ messages,
    const int*   __restrict__ adj,
    const float* __restrict__ w_attn,
    float*       __restrict__ out)
{
    __shared__ float wat[DD * 65];             // w_attn^T, pad 65
    __shared__ ull   redu[8][32][5][2];        // 20 KB
    __shared__ float pre[QT][3][DD];

    const int x    = threadIdx.x;
    const int y    = threadIdx.y;
    const int tid  = y * 32 + x;
    const int b    = blockIdx.x >> 6;          // NQ/QT = 64 q-tiles per batch
    const int q0   = (blockIdx.x & 63) * QT;
    const int half = x >> 4;                   // 0: even q of pair, 1: odd q
    const int m    = x & 15;                   // channel group 4m..4m+3

    // w_attn -> smem transposed now; consumed only after the mainloop
    for (int i = tid; i < DD * DD; i += 256) {
        int e = i >> 6, d = i & 63;
        wat[d * 65 + e] = w_attn[i];
    }

    // Accumulators: A[pair][kind][h]; kind 0:s 1:s2 2..4:a0..a2; h = channel half
    ull A[4][5][2];
    #pragma unroll
    for (int j = 0; j < 4; ++j)
        #pragma unroll
        for (int kk = 0; kk < 5; ++kk) { A[j][kk][0] = 0ull; A[j][kk][1] = 0ull; }

    const float L2EF = __uint_as_float(0x3FB8AA3Bu);   // log2(e), same as __expf

    // per-lane byte cursors
    // msg element: ((b*NQ + q0 + 2j + half)*NKV + k)*64 + 4m ; pair stride 2 q rows
    const char* mpc = (const char*)messages
                    + (((size_t)(b * NQ + q0 + half) * NKV + y) * DD + 4 * m) * 4;
    // proj element: (b*NKV + k)*192 + c*64 + 4m
    const char* ppc = (const char*)g_proj
                    + (((size_t)b * NKV + y) * 192 + 4 * m) * 4;

    // proj depth-1: pj holds stage s, ppc points at stage s+1
    ull pj[3][2];
    LDG2U64(pj[0][0], pj[0][1], ppc);
    LDG2U64(pj[1][0], pj[1][1], ppc + 256);
    LDG2U64(pj[2][0], pj[2][1], ppc + 512);
    ppc += 6144;

    const int* adjb = adj + ((size_t)b * NQ + q0) * NKV;
    ull buf[4][2];

    #pragma unroll 1
    for (int h = 0; h < 2; ++h) {
        // ballots: mk[q] bit i = adj(q, k = y + 256h + 8i), warp-uniform
        unsigned mk[8];
        #pragma unroll
        for (int q = 0; q < 8; ++q)
            mk[q] = __ballot_sync(0xffffffffu, adjb[q * NKV + y + 256 * h + 8 * x] > 0);
        // per-lane pair mask: even q for lanes 0-15, odd q for lanes 16-31
        unsigned merged[4];
        #pragma unroll
        for (int j = 0; j < 4; ++j)
            merged[j] = (x < 16) ? mk[2 * j] : mk[2 * j + 1];

        // prime stage 32h
        #pragma unroll
        for (int j = 0; j < 4; ++j)
            PLDU128(buf[j][0], buf[j][1], merged[j] & 1u, mpc + j * 262144);
        const char* rc = mpc + 2048;           // refill cursor: stage 32h+1
        mpc += 65536;

        unsigned bit = 1u;
        #pragma unroll 1
        for (int i = 0; i < 32; ++i) {
            const unsigned bitn = bit << 1;    // 0 at i=31 -> refill squashed

            #pragma unroll
            for (int j = 0; j < 4; ++j) {
                float f0, f1, f2, f3;
                UNPACK2(f0, f1, buf[j][0]);
                UNPACK2(f2, f3, buf[j][1]);
                PLDU128(buf[j][0], buf[j][1], merged[j] & bitn, rc + j * 262144);
                float e0, e1, e2, e3;
                EX2(e0, f0 * L2EF); EX2(e1, f1 * L2EF);
                EX2(e2, f2 * L2EF); EX2(e3, f3 * L2EF);
                ull ev0, ev1;
                PACK2(ev0, e0, e1); PACK2(ev1, e2, e3);
                ADD2(A[j][0][0], A[j][0][0], ev0);  ADD2(A[j][0][1], A[j][0][1], ev1);
                FMA2(A[j][1][0], ev0, ev0, A[j][1][0]);
                FMA2(A[j][1][1], ev1, ev1, A[j][1][1]);
                FMA2(A[j][2][0], ev0, pj[0][0], A[j][2][0]);
                FMA2(A[j][2][1], ev1, pj[0][1], A[j][2][1]);
                FMA2(A[j][3][0], ev0, pj[1][0], A[j][3][0]);
                FMA2(A[j][3][1], ev1, pj[1][1], A[j][3][1]);
                FMA2(A[j][4][0], ev0, pj[2][0], A[j][4][0]);
                FMA2(A[j][4][1], ev1, pj[2][1], A[j][4][1]);
            }
            // proj refill for next stage (unconditional; pad absorbs overrun)
            LDG2U64(pj[0][0], pj[0][1], ppc);
            LDG2U64(pj[1][0], pj[1][1], ppc + 256);
            LDG2U64(pj[2][0], pj[2][1], ppc + 512);
            ppc += 6144;
            rc  += 2048;
            bit  = bitn;
        }
    }

    // Stage 3: reduce 8 k-slices, one PAIR (2 q's) per pass; fold weights:
    // pre[c][d] = acc_c * sqrt(s2) / s^2
    #pragma unroll 1
    for (int j = 0; j < 4; ++j) {
        __syncthreads();
        #pragma unroll
        for (int kk = 0; kk < 5; ++kk) {
            redu[y][x][kk][0] = A[j][kk][0];
            redu[y][x][kk][1] = A[j][kk][1];
        }
        __syncthreads();
        if (tid < 64) {
            const int dlt = tid >> 5;          // which q of the pair
            const int xx  = tid & 31;          // channel pair 2xx, 2xx+1
            const int l   = dlt * 16 + (xx >> 1);
            const int hh  = xx & 1;
            ull S0 = redu[0][l][0][hh], S1 = redu[0][l][1][hh];
            ull S2 = redu[0][l][2][hh], S3 = redu[0][l][3][hh], S4 = redu[0][l][4][hh];
            #pragma unroll
            for (int yy = 1; yy < 8; ++yy) {
                ADD2(S0, S0, redu[yy][l][0][hh]);
                ADD2(S1, S1, redu[yy][l][1][hh]);
                ADD2(S2, S2, redu[yy][l][2][hh]);
                ADD2(S3, S3, redu[yy][l][3][hh]);
                ADD2(S4, S4, redu[yy][l][4][hh]);
            }
            float Sx, Sy, S2x, S2y, ax, ay;
            UNPACK2(Sx, Sy, S0);
            UNPACK2(S2x, S2y, S1);
            const float scx = sqrtf(S2x) / (Sx * Sx);
            const float scy = sqrtf(S2y) / (Sy * Sy);
            const int q = 2 * j + dlt;
            float2* pre2 = (float2*)pre;
            UNPACK2(ax, ay, S2); pre2[(q * 3 + 0) * 32 + xx] = make_float2(ax * scx, ay * scy);
            UNPACK2(ax, ay, S3); pre2[(q * 3 + 1) * 32 + xx] = make_float2(ax * scx, ay * scy);
            UNPACK2(ax, ay, S4); pre2[(q * 3 + 2) * 32 + xx] = make_float2(ax * scx, ay * scy);
        }
    }
    __syncthreads();

    // Stage 4: out[q,c,e] = sum_d pre[q,c,d] * w_attn[e,d]   (QT*3*64 = 1536)
    float* outb = out + (size_t)(b * NQ + q0) * (3 * DD);
    #pragma unroll
    for (int jj = 0; jj < 6; ++jj) {
        const int oid = tid + jj * 256;        // (q*3+c)*64 + e
        const int e  = oid & 63;
        const int cq = oid >> 6;
        const int c  = cq % 3, q = cq / 3;
        float acc = 0.f;
        #pragma unroll
        for (int d = 0; d < DD; ++d)
            acc += pre[q][c][d] * wat[d * 65 + e];
        outb[oid] = acc;
    }
}

// ---------------------------------------------------------------------------
extern "C" void kernel_launch(void* const* d_in, const int* in_sizes, int n_in,
                              void* d_out, int out_size)
{
    const float* v_equi   = (const float*)d_in[0];
    const float* messages = (const float*)d_in[1];
    const int*   adj      = (const int*)d_in[2];
    const float* w_coord  = (const float*)d_in[3];
    const float* w_attn   = (const float*)d_in[4];
    float* out = (float*)d_out;

    const int B = in_sizes[2] / (NQ * NKV);    // adj element count -> batch

    proj_kernel<<<B * NKV / 8, 192>>>(v_equi, w_coord);

    dim3 blk(32, 8);
    attn_kernel<<<B * (NQ / QT), blk>>>(messages, adj, w_attn, out);
}

// round 13
// speedup vs baseline: 1.1431x; 1.0967x over previous
#include <cuda_runtime.h>

#define NQ  512
#define NKV 512
#define DD  64
#define QT  8

typedef unsigned long long ull;

// proj scratch [b][k][c][e]; pad covers depth-1 prefetch overrun past k=511
__device__ __align__(256) float g_proj[4 * NKV * 3 * DD + 8192];

// ---- packed fp32x2 math (per-lane IEEE fp32, identical rounding to scalar) ----
#define PACK2(d, lo, hi)   asm("mov.b64 %0, {%1, %2};" : "=l"(d) : "f"(lo), "f"(hi))
#define UNPACK2(lo, hi, s) asm("mov.b64 {%0, %1}, %2;" : "=f"(lo), "=f"(hi) : "l"(s))
#define FMA2(d, a, b, c)   asm("fma.rn.f32x2 %0, %1, %2, %3;" : "=l"(d) : "l"(a), "l"(b), "l"(c))
#define ADD2(d, a, b)      asm("add.rn.f32x2 %0, %1, %2;" : "=l"(d) : "l"(a), "l"(b))
// e = ex2(m * log2e) with the exact log2e constant __expf lowers to
#define EX2(d, a)          asm("ex2.approx.f32 %0, %1;" : "=f"(d) : "f"(a))

#define LDG2U64(lo, hi, ptr)                                            \
    asm("ld.global.nc.v2.u64 {%0,%1}, [%2];" : "=l"(lo), "=l"(hi) : "l"(ptr))

// Predicated 16B async copy; flag==0 -> NO DRAM request, smem untouched.
// Addresses are registers; after unrolling, constant offsets fold into LEA.
#define CPA16(saddr, gptr, flag)                                        \
    asm volatile("{\n\t.reg .pred p;\n\t"                               \
                 "setp.ne.u32 p, %2, 0;\n\t"                            \
                 "@p cp.async.cg.shared.global [%0], [%1], 16;\n\t}"    \
                 :: "r"(saddr), "l"(gptr), "r"(flag) : "memory")
#define CPCOMMIT() asm volatile("cp.async.commit_group;" ::: "memory")
#define CPWAIT3()  asm volatile("cp.async.wait_group 3;" ::: "memory")
#define CPWAIT0()  asm volatile("cp.async.wait_group 0;" ::: "memory")

#define LDS128F(f0, f1, f2, f3, saddr)                                  \
    asm("ld.shared.v4.f32 {%0,%1,%2,%3}, [%4];"                         \
        : "=f"(f0), "=f"(f1), "=f"(f2), "=f"(f3) : "r"(saddr))

// ---------------------------------------------------------------------------
// Kernel A: proj[b,k,c,e] = sum_d v_equi[b,k,c,d] * w_coord[e,d]
// ---------------------------------------------------------------------------
__global__ __launch_bounds__(192) void proj_kernel(const float* __restrict__ v,
                                                   const float* __restrict__ w)
{
    __shared__ float ws[DD][68];
    __shared__ float vs[8 * 3 * DD];

    const int tid = threadIdx.x;
    const float4* w4 = (const float4*)w;
    for (int i = tid; i < DD * DD / 4; i += 192) {
        float4 t = w4[i];
        int e = i >> 4, d = (i & 15) * 4;
        *(float4*)&ws[e][d] = t;
    }
    const int bk0 = blockIdx.x * 8;
    const float4* v4 = (const float4*)(v + (size_t)bk0 * 3 * DD);
    for (int i = tid; i < 8 * 3 * DD / 4; i += 192)
        ((float4*)vs)[i] = v4[i];
    __syncthreads();

    const int c = tid / DD, e = tid % DD;
    float acc[8];
    #pragma unroll
    for (int kk = 0; kk < 8; ++kk) acc[kk] = 0.f;

    #pragma unroll 4
    for (int d4 = 0; d4 < 16; ++d4) {
        const float4 wv = *(const float4*)&ws[e][d4 * 4];
        #pragma unroll
        for (int kk = 0; kk < 8; ++kk) {
            const float4 vv = *(const float4*)&vs[(kk * 3 + c) * DD + d4 * 4];
            acc[kk] += vv.x * wv.x + vv.y * wv.y + vv.z * wv.z + vv.w * wv.w;
        }
    }
    #pragma unroll
    for (int kk = 0; kk < 8; ++kk)
        g_proj[(size_t)(bk0 + kk) * (3 * DD) + c * DD + e] = acc[kk];
}

// ---------------------------------------------------------------------------
// Kernel B: fused masked-softmax attention + L2-norm weighting + w_attn proj.
// Block = (b, 8 q's); grid = 256 -> single wave at 2 CTAs/SM.
// y = k-slice (k = y + 8*stage). q's in PAIRS: lanes 0-15 = even q (channels
// 4m..4m+3), lanes 16-31 = odd q. Messages flow through a per-warp depth-4
// cp.async.cg ring (8 KB/warp, 64 KB/CTA dynamic smem): each lane copies and
// later consumes its own 16 B -> per-warp wait_group, zero barriers, depth
// decoupled from registers. Masked k: cp.async squashed (no DRAM), consume
// side SELs to -inf before ex2 -> exact 0 contribution (matches reference
// fp32 underflow of exp(-1e10-max)).
// ---------------------------------------------------------------------------
__global__ __launch_bounds__(256, 2) void attn_kernel(
    const float* __restrict__ messages,
    const int*   __restrict__ adj,
    const float* __restrict__ w_attn,
    float*       __restrict__ out)
{
    extern __shared__ char dsm[];              // 64 KB ring; aliased epilogue

    const int x    = threadIdx.x;
    const int y    = threadIdx.y;
    const int tid  = y * 32 + x;
    const int b    = blockIdx.x >> 6;          // NQ/QT = 64 q-tiles per batch
    const int q0   = (blockIdx.x & 63) * QT;
    const int half = x >> 4;                   // 0: even q of pair, 1: odd q
    const int m    = x & 15;                   // channel group 4m..4m+3

    // ring layout: [y][slot 0..3][pair 0..3][lane 0..31] * 16 B
    const unsigned rbase =
        (unsigned)__cvta_generic_to_shared(dsm) + y * 8192 + x * 16;

    // Masks as 64-bit shift registers per PAIR (lane-selected even/odd q).
    // bit i of (mhi:mlo) = adj(q_pair, k = y + 8i) = stage i.
    unsigned mlo[4], mhi[4];
    {
        const int* adjb = adj + ((size_t)b * NQ + q0) * NKV;
        #pragma unroll
        for (int j = 0; j < 4; ++j) {
            unsigned le = __ballot_sync(~0u, adjb[(2 * j) * NKV + y + 8 * x] > 0);
            unsigned lo = __ballot_sync(~0u, adjb[(2 * j + 1) * NKV + y + 8 * x] > 0);
            unsigned he = __ballot_sync(~0u, adjb[(2 * j) * NKV + y + 256 + 8 * x] > 0);
            unsigned ho = __ballot_sync(~0u, adjb[(2 * j + 1) * NKV + y + 256 + 8 * x] > 0);
            mlo[j] = (x < 16) ? le : lo;
            mhi[j] = (x < 16) ? he : ho;
        }
    }

    // Accumulators A[pair][kind][chan-half]; kind 0:s 1:s2 2..4:a0..a2
    ull A[4][5][2];
    #pragma unroll
    for (int j = 0; j < 4; ++j)
        #pragma unroll
        for (int kk = 0; kk < 5; ++kk) { A[j][kk][0] = 0ull; A[j][kk][1] = 0ull; }

    const float L2EF   = __uint_as_float(0x3FB8AA3Bu);
    const float NEGINF = __int_as_float((int)0xFF800000);

    // msg byte cursor: element ((b*NQ+q0+2j+half)*NKV + y+8s)*64 + 4m floats.
    // q-pair j offset = j * 2 q-rows = j * 2*NKV*DD*4 bytes = j * 262144.
    const char* msrc = (const char*)messages
                     + (((size_t)(b * NQ + q0 + half) * NKV + y) * DD + 4 * m) * 4;
    // proj byte cursor: element ((b*NKV + k)*3 + c)*64 + 4m floats
    const char* ppc = (const char*)g_proj
                    + (((size_t)b * NKV + y) * 192 + 4 * m) * 4;

    // proj depth-1: pj holds stage s, ppc points at stage s+1
    ull pj[3][2];
    LDG2U64(pj[0][0], pj[0][1], ppc);
    LDG2U64(pj[1][0], pj[1][1], ppc + 256);
    LDG2U64(pj[2][0], pj[2][1], ppc + 512);
    ppc += 6144;

    // ---- prime ring stages 0..2 into slots 0..2 ----
    #pragma unroll
    for (int st = 0; st < 3; ++st) {
        #pragma unroll
        for (int j = 0; j < 4; ++j)
            CPA16(rbase + st * 2048 + j * 512,
                  msrc + st * 2048 + j * 262144,
                  mlo[j] & (1u << st));
        CPCOMMIT();
    }

    const char* psrc = msrc + 3 * 2048;        // prefetch cursor: stage s+3

    #pragma unroll 1
    for (int o = 0; o < 16; ++o) {
        #pragma unroll
        for (int t = 0; t < 4; ++t) {
            // prefetch stage 4o+t+3 into slot (t+3)&3
            #pragma unroll
            for (int j = 0; j < 4; ++j)
                CPA16(rbase + (((t + 3) & 3) * 2048) + j * 512,
                      psrc + j * 262144,
                      mlo[j] & (8u << t));
            psrc += 2048;
            CPCOMMIT();
            CPWAIT3();                          // stage 4o+t resident

            #pragma unroll
            for (int j = 0; j < 4; ++j) {
                float f0, f1, f2, f3;
                LDS128F(f0, f1, f2, f3, rbase + t * 2048 + j * 512);
                const unsigned cf = mlo[j] & (1u << t);
                float g0 = cf ? f0 : NEGINF;
                float g1 = cf ? f1 : NEGINF;
                float g2 = cf ? f2 : NEGINF;
                float g3 = cf ? f3 : NEGINF;
                float e0, e1, e2, e3;
                EX2(e0, g0 * L2EF); EX2(e1, g1 * L2EF);
                EX2(e2, g2 * L2EF); EX2(e3, g3 * L2EF);
                ull ev0, ev1;
                PACK2(ev0, e0, e1); PACK2(ev1, e2, e3);
                ADD2(A[j][0][0], A[j][0][0], ev0);  ADD2(A[j][0][1], A[j][0][1], ev1);
                FMA2(A[j][1][0], ev0, ev0, A[j][1][0]);
                FMA2(A[j][1][1], ev1, ev1, A[j][1][1]);
                FMA2(A[j][2][0], ev0, pj[0][0], A[j][2][0]);
                FMA2(A[j][2][1], ev1, pj[0][1], A[j][2][1]);
                FMA2(A[j][3][0], ev0, pj[1][0], A[j][3][0]);
                FMA2(A[j][3][1], ev1, pj[1][1], A[j][3][1]);
                FMA2(A[j][4][0], ev0, pj[2][0], A[j][4][0]);
                FMA2(A[j][4][1], ev1, pj[2][1], A[j][4][1]);
            }
            // proj refill for next stage (unconditional; pad absorbs overrun)
            LDG2U64(pj[0][0], pj[0][1], ppc);
            LDG2U64(pj[1][0], pj[1][1], ppc + 256);
            LDG2U64(pj[2][0], pj[2][1], ppc + 512);
            ppc += 6144;
        }
        #pragma unroll
        for (int j = 0; j < 4; ++j) {
            mlo[j] = __funnelshift_r(mlo[j], mhi[j], 4);
            mhi[j] >>= 4;
        }
    }

    CPWAIT0();                                  // ring fully drained
    __syncthreads();                            // before aliased epilogue smem

    // ---- aliased epilogue layout over the (dead) ring ----
    float* wat = (float*)dsm;                                  // 16640 B
    ull (*redu)[32][5][2] = (ull (*)[32][5][2])(dsm + 16640);  // 20480 B
    float (*pre)[3][DD]   = (float (*)[3][DD])(dsm + 37120);   // 6144 B

    // w_attn -> smem transposed, pad 65
    for (int i = tid; i < DD * DD; i += 256) {
        int e = i >> 6, d = i & 63;
        wat[d * 65 + e] = w_attn[i];
    }

    // Stage 3: reduce 8 k-slices, one PAIR (2 q's) per pass; fold weights:
    // pre[c][d] = acc_c * sqrt(s2) / s^2
    #pragma unroll 1
    for (int j = 0; j < 4; ++j) {
        __syncthreads();
        #pragma unroll
        for (int kk = 0; kk < 5; ++kk) {
            redu[y][x][kk][0] = A[j][kk][0];
            redu[y][x][kk][1] = A[j][kk][1];
        }
        __syncthreads();
        if (tid < 64) {
            const int dlt = tid >> 5;          // which q of the pair
            const int xx  = tid & 31;          // channel pair 2xx, 2xx+1
            const int l   = dlt * 16 + (xx >> 1);
            const int hh  = xx & 1;
            ull S0 = redu[0][l][0][hh], S1 = redu[0][l][1][hh];
            ull S2 = redu[0][l][2][hh], S3 = redu[0][l][3][hh], S4 = redu[0][l][4][hh];
            #pragma unroll
            for (int yy = 1; yy < 8; ++yy) {
                ADD2(S0, S0, redu[yy][l][0][hh]);
                ADD2(S1, S1, redu[yy][l][1][hh]);
                ADD2(S2, S2, redu[yy][l][2][hh]);
                ADD2(S3, S3, redu[yy][l][3][hh]);
                ADD2(S4, S4, redu[yy][l][4][hh]);
            }
            float Sx, Sy, S2x, S2y, ax, ay;
            UNPACK2(Sx, Sy, S0);
            UNPACK2(S2x, S2y, S1);
            const float scx = sqrtf(S2x) / (Sx * Sx);
            const float scy = sqrtf(S2y) / (Sy * Sy);
            const int q = 2 * j + dlt;
            float2* pre2 = (float2*)pre;
            UNPACK2(ax, ay, S2); pre2[(q * 3 + 0) * 32 + xx] = make_float2(ax * scx, ay * scy);
            UNPACK2(ax, ay, S3); pre2[(q * 3 + 1) * 32 + xx] = make_float2(ax * scx, ay * scy);
            UNPACK2(ax, ay, S4); pre2[(q * 3 + 2) * 32 + xx] = make_float2(ax * scx, ay * scy);
        }
    }
    __syncthreads();

    // Stage 4: out[q,c,e] = sum_d pre[q,c,d] * w_attn[e,d]   (QT*3*64 = 1536)
    float* outb = out + (size_t)(b * NQ + q0) * (3 * DD);
    #pragma unroll
    for (int jj = 0; jj < 6; ++jj) {
        const int oid = tid + jj * 256;        // (q*3+c)*64 + e
        const int e  = oid & 63;
        const int cq = oid >> 6;
        const int c  = cq % 3, q = cq / 3;
        float acc = 0.f;
        #pragma unroll
        for (int d = 0; d < DD; ++d)
            acc += pre[q][c][d] * wat[d * 65 + e];
        outb[oid] = acc;
    }
}

// ---------------------------------------------------------------------------
extern "C" void kernel_launch(void* const* d_in, const int* in_sizes, int n_in,
                              void* d_out, int out_size)
{
    const float* v_equi   = (const float*)d_in[0];
    const float* messages = (const float*)d_in[1];
    const int*   adj      = (const int*)d_in[2];
    const float* w_coord  = (const float*)d_in[3];
    const float* w_attn   = (const float*)d_in[4];
    float* out = (float*)d_out;

    const int B = in_sizes[2] / (NQ * NKV);    // adj element count -> batch

    proj_kernel<<<B * NKV / 8, 192>>>(v_equi, w_coord);

    cudaFuncSetAttribute(attn_kernel,
                         cudaFuncAttributeMaxDynamicSharedMemorySize, 65536);
    dim3 blk(32, 8);
    attn_kernel<<<B * (NQ / QT), blk, 65536>>>(messages, adj, w_attn, out);
}